// round 16
// baseline (speedup 1.0000x reference)
#include <cuda_runtime.h>
#include <cuda_bf16.h>
#include <cstdint>

#define Dsz 768
#define Bsz 2
#define Ssz 256
#define NV  765
#define TOT 32896
#define PD  128
#define HS  393216L        // 512*768 (z stride in elems)
#define WS  589824L        // 768*768
#define PADROWS (TOT - NV) // 32131

typedef __nv_bfloat16 bf16;
typedef __nv_bfloat162 bf162;

// ---------------- scratch (device globals; no allocation) ------------------
__device__ __align__(16) bf16 g_hh[Bsz*Ssz*Dsz], g_hl[Bsz*Ssz*Dsz];     // hidden hi/lo
__device__ __align__(16) bf16 g_wsTh[2*WS],      g_wsTl[2*WS];          // w_span[z]^T hi/lo
__device__ __align__(16) bf16 g_wp1Th[WS],       g_wp1Tl[WS];           // w_p1^T hi/lo
__device__ __align__(16) bf16 g_wp2Th[PD*Dsz],   g_wp2Tl[PD*Dsz];       // w_p2^T hi/lo
__device__ __align__(16) bf16 g_Hh[2*Bsz*Ssz*Dsz], g_Hl[2*Bsz*Ssz*Dsz]; // H hi/lo
__device__ __align__(16) float g_A[2*Bsz*Ssz*Dsz];                      // A fp32
__device__ float g_W3[3*Dsz];
__device__ float g_C[4*Dsz];          // 0..2: (W3[w]+b_span)@w_p1+b_p1 ; 3: cpad
__device__ float g_L[1028];
__device__ __align__(16) float g_projpad[PD];
__device__ float g_zero[Dsz];

// ---------------------------------------------------------------------------
__device__ __forceinline__ void mma_bf16(float* c, const unsigned* a,
                                         const unsigned* b) {
    asm volatile(
        "mma.sync.aligned.m16n8k16.row.col.f32.bf16.bf16.f32 "
        "{%0,%1,%2,%3}, {%4,%5,%6,%7}, {%8,%9}, {%0,%1,%2,%3};"
        : "+f"(c[0]), "+f"(c[1]), "+f"(c[2]), "+f"(c[3])
        : "r"(a[0]), "r"(a[1]), "r"(a[2]), "r"(a[3]), "r"(b[0]), "r"(b[1]));
}

#define KST 24

// ---------------------------------------------------------------------------
// MMA GEMM tile (validated R9/R12/R15): D[64x64] = A[64x768] * B[64x768]^T
// bf16 hi/lo split, fp32 accum.  128 thr, 4 warps 32x32, 48 chunks of 16-K.
// ---------------------------------------------------------------------------
__device__ void tmma_body(int e,
    const bf16* __restrict__ Ah0, const bf16* __restrict__ Al0, long aZ,
    const bf16* __restrict__ Bh0, const bf16* __restrict__ Bl0, long bZ,
    int outMode)
{
    __shared__ __align__(16) bf16 sA[2][2][64][KST];
    __shared__ __align__(16) bf16 sB[2][2][64][KST];

    const int z = e / 96, r = e % 96;
    const int row0 = (r / 12) * 64, n0 = (r % 12) * 64;
    const bf16* Ah = Ah0 + (long)z * aZ;
    const bf16* Al = Al0 + (long)z * aZ;
    const bf16* Bh = Bh0 + (long)z * bZ;
    const bf16* Bl = Bl0 + (long)z * bZ;

    const int tid = threadIdx.x, wid = tid >> 5, lane = tid & 31;
    const int wr = wid >> 1, wc = wid & 1;
    const int gid = lane >> 2, kp = lane & 3;

    const int lr = tid >> 1, lh = (tid & 1) * 8;
    const long aoff = (long)(row0 + lr) * Dsz + lh;
    const long boff = (long)(n0 + lr) * Dsz + lh;

    float acc[2][4][4] = {};
    uint4 pAh, pAl, pBh, pBl;

    pAh = *(const uint4*)(Ah + aoff);
    pAl = *(const uint4*)(Al + aoff);
    pBh = *(const uint4*)(Bh + boff);
    pBl = *(const uint4*)(Bl + boff);
    *(uint4*)&sA[0][0][lr][lh] = pAh;
    *(uint4*)&sA[0][1][lr][lh] = pAl;
    *(uint4*)&sB[0][0][lr][lh] = pBh;
    *(uint4*)&sB[0][1][lr][lh] = pBl;
    __syncthreads();

    for (int it = 0; it < 48; it++) {
        const int cur = it & 1;
        if (it + 1 < 48) {
            const int kb = (it + 1) * 16;
            pAh = *(const uint4*)(Ah + aoff + kb);
            pAl = *(const uint4*)(Al + aoff + kb);
            pBh = *(const uint4*)(Bh + boff + kb);
            pBl = *(const uint4*)(Bl + boff + kb);
        }

        unsigned ah[2][4], al[2][4], bh[4][2], bl[4][2];
        #pragma unroll
        for (int mt = 0; mt < 2; mt++) {
            const int r0 = wr * 32 + mt * 16 + gid;
            ah[mt][0] = *(const unsigned*)&sA[cur][0][r0][kp * 2];
            ah[mt][1] = *(const unsigned*)&sA[cur][0][r0 + 8][kp * 2];
            ah[mt][2] = *(const unsigned*)&sA[cur][0][r0][kp * 2 + 8];
            ah[mt][3] = *(const unsigned*)&sA[cur][0][r0 + 8][kp * 2 + 8];
            al[mt][0] = *(const unsigned*)&sA[cur][1][r0][kp * 2];
            al[mt][1] = *(const unsigned*)&sA[cur][1][r0 + 8][kp * 2];
            al[mt][2] = *(const unsigned*)&sA[cur][1][r0][kp * 2 + 8];
            al[mt][3] = *(const unsigned*)&sA[cur][1][r0 + 8][kp * 2 + 8];
        }
        #pragma unroll
        for (int nt = 0; nt < 4; nt++) {
            const int rb = wc * 32 + nt * 8 + gid;
            bh[nt][0] = *(const unsigned*)&sB[cur][0][rb][kp * 2];
            bh[nt][1] = *(const unsigned*)&sB[cur][0][rb][kp * 2 + 8];
            bl[nt][0] = *(const unsigned*)&sB[cur][1][rb][kp * 2];
            bl[nt][1] = *(const unsigned*)&sB[cur][1][rb][kp * 2 + 8];
        }
        #pragma unroll
        for (int mt = 0; mt < 2; mt++)
            #pragma unroll
            for (int nt = 0; nt < 4; nt++) {
                mma_bf16(acc[mt][nt], ah[mt], bh[nt]);
                mma_bf16(acc[mt][nt], ah[mt], bl[nt]);
                mma_bf16(acc[mt][nt], al[mt], bh[nt]);
            }

        if (it + 1 < 48) {
            const int nb = cur ^ 1;
            *(uint4*)&sA[nb][0][lr][lh] = pAh;
            *(uint4*)&sA[nb][1][lr][lh] = pAl;
            *(uint4*)&sB[nb][0][lr][lh] = pBh;
            *(uint4*)&sB[nb][1][lr][lh] = pBl;
            __syncthreads();
        }
    }

    #pragma unroll
    for (int mt = 0; mt < 2; mt++) {
        const int grow = row0 + wr * 32 + mt * 16 + gid;
        const long gr0 = ((long)z * 512 + grow) * Dsz;
        const long gr1 = gr0 + 8L * Dsz;
        #pragma unroll
        for (int nt = 0; nt < 4; nt++) {
            const int gc = n0 + wc * 32 + nt * 8 + kp * 2;
            const float* cc = acc[mt][nt];
            if (outMode == 1) {
                bf162 h01 = __floats2bfloat162_rn(cc[0], cc[1]);
                bf162 l01 = __floats2bfloat162_rn(cc[0] - __low2float(h01),
                                                  cc[1] - __high2float(h01));
                bf162 h23 = __floats2bfloat162_rn(cc[2], cc[3]);
                bf162 l23 = __floats2bfloat162_rn(cc[2] - __low2float(h23),
                                                  cc[3] - __high2float(h23));
                *(bf162*)&g_Hh[gr0 + gc] = h01;
                *(bf162*)&g_Hl[gr0 + gc] = l01;
                *(bf162*)&g_Hh[gr1 + gc] = h23;
                *(bf162*)&g_Hl[gr1 + gc] = l23;
            } else {
                float2 v0 = { cc[0], cc[1] }, v1 = { cc[2], cc[3] };
                *(float2*)&g_A[gr0 + gc] = v0;
                *(float2*)&g_A[gr1 + gc] = v1;
            }
        }
    }
}

// ---------------------------------------------------------------------------
// GEMV helpers (validated)
// ---------------------------------------------------------------------------
__device__ __forceinline__ void gemv256(
    const float* __restrict__ a1, const float* __restrict__ a2, int mode,
    const float* __restrict__ W, int ldw,
    const float* __restrict__ bias, float* __restrict__ out,
    int n0, char* raw)
{
    float (*red)[64] = (float(*)[64])raw;
    const int tid = threadIdx.x;
    const int nl = tid & 63, kg = tid >> 6;
    const int n = n0 + nl;
    float s = 0.f;
    const int k0 = kg * 192;
    #pragma unroll 8
    for (int t = 0; t < 192; t++) {
        int k = k0 + t;
        float av = a1[k];
        if (mode == 1) av += a2[k];
        else if (mode == 2) av = fmaxf(av, 0.f);
        s += av * W[(long)k * ldw + n];
    }
    red[kg][nl] = s;
    __syncthreads();
    if (kg == 0)
        out[n] = red[0][nl] + red[1][nl] + red[2][nl] + red[3][nl] + bias[n];
}

__device__ __forceinline__ void gemv128(
    const float* __restrict__ a1, const float* __restrict__ a2, int mode,
    const float* __restrict__ W, int ldw,
    const float* __restrict__ bias, float* __restrict__ out, int n0)
{
    __shared__ float red[2][64];
    const int tid = threadIdx.x;
    const int nl = tid & 63, kg = tid >> 6;
    const int n = n0 + nl;
    float s = 0.f;
    const int k0 = kg * 384;
    #pragma unroll 8
    for (int t = 0; t < 384; t++) {
        int k = k0 + t;
        float av = a1[k];
        if (mode == 1) av += a2[k];
        else if (mode == 2) av = fmaxf(av, 0.f);
        s += av * W[(long)k * ldw + n];
    }
    red[kg][nl] = s;
    __syncthreads();
    if (kg == 0) out[n] = red[0][nl] + red[1][nl] + bias[n];
}

// transpose+convert one 64x64 tile: src [k][n] fp32 -> dh/dl [n][k] bf16
__device__ __forceinline__ void tcvt_tile(const float* __restrict__ src, int lds,
                                          bf16* __restrict__ dh, bf16* __restrict__ dl,
                                          int k0, int n0, char* raw)
{
    int tid = threadIdx.x;
    float (*ts)[65] = (float(*)[65])raw;
    {
        int r = tid >> 2, cs = (tid & 3) * 16;
        const float* sp = src + (long)(k0 + r) * lds + n0 + cs;
        #pragma unroll
        for (int i = 0; i < 16; i++) ts[r][cs + i] = sp[i];
    }
    __syncthreads();
    {
        int rr = tid >> 2, ks = (tid & 3) * 16;
        long go = (long)(n0 + rr) * Dsz + k0 + ks;
        #pragma unroll
        for (int i = 0; i < 16; i++) {
            float x = ts[ks + i][rr];
            bf16 h = __float2bfloat16(x);
            dh[go + i] = h;
            dl[go + i] = __float2bfloat16(x - __bfloat162float(h));
        }
    }
}

// ---------------------------------------------------------------------------
// M0 (256 thr): [0,288) w_span T+cvt ; [288,480) hidden cvt
// ---------------------------------------------------------------------------
__global__ void M0_k(const float* __restrict__ hidden,
                     const float* __restrict__ w_span)
{
    __shared__ __align__(16) char raw[64 * 65 * 4];
    int e = blockIdx.x, tid = threadIdx.x;
    if (e < 288) {
        int m = e / 144, t = e % 144;
        int tr = t / 12, tc = t % 12;
        tcvt_tile(w_span + (long)m * WS, Dsz,
                  g_wsTh + (long)m * WS, g_wsTl + (long)m * WS,
                  tc * 64, tr * 64, raw);
    } else {
        long base = (long)(e - 288) * 2048 + tid * 8;
        float4 a = *(const float4*)(hidden + base);
        float4 b = *(const float4*)(hidden + base + 4);
        float xs[8] = { a.x, a.y, a.z, a.w, b.x, b.y, b.z, b.w };
        __align__(16) bf16 h8[8], l8[8];
        #pragma unroll
        for (int i = 0; i < 8; i++) {
            bf16 h = __float2bfloat16(xs[i]);
            h8[i] = h;
            l8[i] = __float2bfloat16(xs[i] - __bfloat162float(h));
        }
        *(uint4*)(g_hh + base) = *(const uint4*)h8;
        *(uint4*)(g_hl + base) = *(const uint4*)l8;
    }
}

// ---------------------------------------------------------------------------
// S1 (256 thr): [0,144) w_p1 T ; [144,168) w_p2 T ; [168,204) W3 ;
//               [204,216) cpad ; [216,264) valid-row b_p2 init
// ---------------------------------------------------------------------------
__global__ void S1_k(const float* __restrict__ w_p1,
                     const float* __restrict__ w_p2,
                     const float* __restrict__ width_emb,
                     const float* __restrict__ w_span,
                     const float* __restrict__ b_span,
                     const float* __restrict__ b_p1,
                     const float* __restrict__ b_p2,
                     float* __restrict__ out)
{
    __shared__ __align__(16) char raw[64 * 65 * 4];
    int e = blockIdx.x, tid = threadIdx.x;
    if (e < 144) {
        int tr = e / 12, tc = e % 12;
        tcvt_tile(w_p1, Dsz, g_wp1Th, g_wp1Tl, tc * 64, tr * 64, raw);
    } else if (e < 168) {
        int t = e - 144;
        tcvt_tile(w_p2, PD, g_wp2Th, g_wp2Tl, (t >> 1) * 64, (t & 1) * 64, raw);
    } else if (e < 204) {
        int g = e - 168, m = g / 12, nb = g % 12;
        gemv256(width_emb + m * Dsz, nullptr, 0,
                w_span + 2L * Dsz * Dsz, Dsz,
                g_zero, g_W3 + m * Dsz, nb * 64, raw);
    } else if (e < 216) {
        int nb = e - 204;
        gemv256(b_span, nullptr, 0, w_p1, Dsz, b_p1, g_C + 3 * Dsz,
                nb * 64, raw);
    } else {
        const long NVAL4 = (long)2 * NV * 32;        // 48960
        long base = (long)(e - 216) * 1024 + tid;
        #pragma unroll
        for (int i = 0; i < 4; i++) {
            long p = base + (long)i * 256;
            if (p < NVAL4) {
                int r = (int)(p >> 5), c = (int)(p & 31);
                int b = r / NV;
                int kv = r - b * NV;
                float4 val = ((const float4*)b_p2)[c];
                long f4 = (long)(Bsz * TOT) / 4 + ((long)b * TOT + kv) * (PD / 4) + c;
                ((float4*)out)[f4] = val;
            }
        }
    }
}

// ---------------------------------------------------------------------------
// M1 (128 thr): GEMM1 (H) only
// ---------------------------------------------------------------------------
__global__ __launch_bounds__(128, 4) void M1_k()
{
    tmma_body(blockIdx.x, g_hh, g_hl, 0L, g_wsTh, g_wsTl, WS, 1);
}

// ---------------------------------------------------------------------------
// S2 (128 thr): [0,36) C rows ; [36,38) projpad
// ---------------------------------------------------------------------------
__global__ void S2_k(const float* __restrict__ b_span,
                     const float* __restrict__ w_p1,
                     const float* __restrict__ b_p1,
                     const float* __restrict__ w_p2,
                     const float* __restrict__ b_p2)
{
    int e = blockIdx.x;
    if (e < 36) {
        int m = e / 12, nb = e % 12;
        gemv128(g_W3 + m * Dsz, b_span, 1, w_p1, Dsz, b_p1,
                g_C + m * Dsz, nb * 64);
    } else {
        int nb = e - 36;
        gemv128(g_C + 3 * Dsz, nullptr, 2, w_p2, PD, b_p2, g_projpad,
                nb * 64);
    }
}

// ---------------------------------------------------------------------------
// S3 (128 thr): fillpad (pad rows <- projpad)
// ---------------------------------------------------------------------------
__global__ void S3_k(float* __restrict__ out)
{
    const long NPAD4 = (long)Bsz * PADROWS * 32;
    long base = (long)blockIdx.x * 1024 + threadIdx.x;
    #pragma unroll
    for (int i = 0; i < 8; i++) {
        long p = base + (long)i * 128;
        if (p < NPAD4) {
            int r = (int)(p >> 5), c = (int)(p & 31);
            int b = r / PADROWS;
            int kk = NV + (r - b * PADROWS);
            float4 val = ((const float4*)g_projpad)[c];
            long f4 = (long)(Bsz * TOT) / 4 + ((long)b * TOT + kk) * (PD / 4) + c;
            ((float4*)out)[f4] = val;
        }
    }
}

// ---------------------------------------------------------------------------
// M2 (128 thr): [0,192) GEMM2 (A) ; [192,449) dots
// ---------------------------------------------------------------------------
__global__ __launch_bounds__(128, 4) void M2_k(
    const float* __restrict__ w_cls, const float* __restrict__ b_cls,
    const float* __restrict__ b_span)
{
    int e = blockIdx.x;
    int tid = threadIdx.x;
    if (e < 192) {
        tmma_body(e, g_Hh, g_Hl, HS, g_wp1Th, g_wp1Tl, 0L, 2);
    } else {
        int gw = (e - 192) * 4 + (tid >> 5);
        int lane = tid & 31;
        if (gw >= 1028) return;
        float s = 0.f;
        if (gw < 1024) {
            int z = gw >> 9, row = gw & 511;
            const bf16* bh = g_Hh + (long)z * HS + (long)row * Dsz;
            const bf16* bl = g_Hl + (long)z * HS + (long)row * Dsz;
            for (int k = lane; k < Dsz; k += 32)
                s += (__bfloat162float(bh[k]) + __bfloat162float(bl[k])) * w_cls[k];
        } else {
            const float* v = (gw < 1027) ? (g_W3 + (gw - 1024) * Dsz) : b_span;
            for (int k = lane; k < Dsz; k += 32) s += v[k] * w_cls[k];
        }
        #pragma unroll
        for (int o = 16; o > 0; o >>= 1) s += __shfl_down_sync(0xffffffffu, s, o);
        if (lane == 0) g_L[gw] = s + (gw == 1027 ? b_cls[0] : 0.f);
    }
}

// ---------------------------------------------------------------------------
// M3 (256 thr): [0,288) spanproj MMA (K-split x6, atomicAdd) ; [288,545) logits
// (identical to R15 P3)
// ---------------------------------------------------------------------------
#define KST2 40
__global__ __launch_bounds__(256) void M3_k(float* __restrict__ out)
{
    int e = blockIdx.x;
    int tid = threadIdx.x;
    if (e < 288) {
        __shared__ __align__(16) bf16 sXh[2][32][KST2], sXl[2][32][KST2];
        __shared__ __align__(16) bf16 sBh[2][128][KST2], sBl[2][128][KST2];
        __shared__ float sD[32][132];
        __shared__ int offA1[32], offA2[32], offC[32];
        __shared__ long offOut[32];

        const int ks6 = e % 6, sg = e / 6;
        const int kbase = ks6 * 128;
        const int wid = tid >> 5, lane = tid & 31;
        const int wr = wid >> 2, wc = wid & 3;
        const int gid = lane >> 2, kp = lane & 3;

        if (tid < 32) {
            int msp = sg * 32 + tid;
            int b = 0, i = 0, w = 0;
            bool valid = msp < 2 * NV;
            int kv = 0;
            if (valid) {
                b = msp / NV; kv = msp - b * NV;
                if (kv < 762)      { i = kv / 3; w = kv - 3 * i; }
                else if (kv < 764) { i = 254;   w = kv - 762;   }
                else               { i = 255;   w = 0;          }
            }
            int j = i + w;
            offA1[tid] = (b * Ssz + i) * Dsz;
            offA2[tid] = (int)HS + (b * Ssz + j) * Dsz;
            offC[tid]  = w * Dsz;
            offOut[tid] = valid ? ((long)Bsz * TOT + ((long)b * TOT + kv) * PD) : -1L;
        }
        __syncthreads();

        const int xs = tid >> 3, xq = (tid & 7) * 4;
        const int br = tid >> 1, bq = (tid & 1) * 16;
        const bf16* pbh = g_wp2Th + (long)br * Dsz;
        const bf16* pbl = g_wp2Tl + (long)br * Dsz;

        float acc[4][4] = {};
        __align__(8) bf16 xh4[4], xl4[4];
        uint4 rbh0, rbh1, rbl0, rbl1;

        {
            const int kb = kbase;
            const float* p1 = g_A + offA1[xs] + kb + xq;
            const float* p2 = g_A + offA2[xs] + kb + xq;
            const float* pc = g_C + offC[xs] + kb + xq;
            #pragma unroll
            for (int i = 0; i < 4; i++) {
                float x = fmaxf(p1[i] + p2[i] + pc[i], 0.f);
                bf16 h = __float2bfloat16(x);
                xh4[i] = h;
                xl4[i] = __float2bfloat16(x - __bfloat162float(h));
            }
            rbh0 = *(const uint4*)(pbh + kb + bq);
            rbh1 = *(const uint4*)(pbh + kb + bq + 8);
            rbl0 = *(const uint4*)(pbl + kb + bq);
            rbl1 = *(const uint4*)(pbl + kb + bq + 8);
            *(uint2*)&sXh[0][xs][xq] = *(const uint2*)xh4;
            *(uint2*)&sXl[0][xs][xq] = *(const uint2*)xl4;
            *(uint4*)&sBh[0][br][bq]     = rbh0;
            *(uint4*)&sBh[0][br][bq + 8] = rbh1;
            *(uint4*)&sBl[0][br][bq]     = rbl0;
            *(uint4*)&sBl[0][br][bq + 8] = rbl1;
        }
        __syncthreads();

        for (int kc = 0; kc < 4; kc++) {
            const int cur = kc & 1;
            if (kc + 1 < 4) {
                const int kb = kbase + (kc + 1) * 32;
                const float* p1 = g_A + offA1[xs] + kb + xq;
                const float* p2 = g_A + offA2[xs] + kb + xq;
                const float* pc = g_C + offC[xs] + kb + xq;
                #pragma unroll
                for (int i = 0; i < 4; i++) {
                    float x = fmaxf(p1[i] + p2[i] + pc[i], 0.f);
                    bf16 h = __float2bfloat16(x);
                    xh4[i] = h;
                    xl4[i] = __float2bfloat16(x - __bfloat162float(h));
                }
                rbh0 = *(const uint4*)(pbh + kb + bq);
                rbh1 = *(const uint4*)(pbh + kb + bq + 8);
                rbl0 = *(const uint4*)(pbl + kb + bq);
                rbl1 = *(const uint4*)(pbl + kb + bq + 8);
            }

            #pragma unroll
            for (int ks = 0; ks < 2; ks++) {
                const int ko = ks * 16;
                unsigned ah[4], al[4], bh[4][2], bl[4][2];
                {
                    const int r0 = wr * 16 + gid;
                    ah[0] = *(const unsigned*)&sXh[cur][r0][kp * 2 + ko];
                    ah[1] = *(const unsigned*)&sXh[cur][r0 + 8][kp * 2 + ko];
                    ah[2] = *(const unsigned*)&sXh[cur][r0][kp * 2 + 8 + ko];
                    ah[3] = *(const unsigned*)&sXh[cur][r0 + 8][kp * 2 + 8 + ko];
                    al[0] = *(const unsigned*)&sXl[cur][r0][kp * 2 + ko];
                    al[1] = *(const unsigned*)&sXl[cur][r0 + 8][kp * 2 + ko];
                    al[2] = *(const unsigned*)&sXl[cur][r0][kp * 2 + 8 + ko];
                    al[3] = *(const unsigned*)&sXl[cur][r0 + 8][kp * 2 + 8 + ko];
                }
                #pragma unroll
                for (int nt = 0; nt < 4; nt++) {
                    const int rb = wc * 32 + nt * 8 + gid;
                    bh[nt][0] = *(const unsigned*)&sBh[cur][rb][kp * 2 + ko];
                    bh[nt][1] = *(const unsigned*)&sBh[cur][rb][kp * 2 + 8 + ko];
                    bl[nt][0] = *(const unsigned*)&sBl[cur][rb][kp * 2 + ko];
                    bl[nt][1] = *(const unsigned*)&sBl[cur][rb][kp * 2 + 8 + ko];
                }
                #pragma unroll
                for (int nt = 0; nt < 4; nt++) {
                    mma_bf16(acc[nt], ah, bh[nt]);
                    mma_bf16(acc[nt], ah, bl[nt]);
                    mma_bf16(acc[nt], al, bh[nt]);
                }
            }

            if (kc + 1 < 4) {
                const int nb = cur ^ 1;
                *(uint2*)&sXh[nb][xs][xq] = *(const uint2*)xh4;
                *(uint2*)&sXl[nb][xs][xq] = *(const uint2*)xl4;
                *(uint4*)&sBh[nb][br][bq]     = rbh0;
                *(uint4*)&sBh[nb][br][bq + 8] = rbh1;
                *(uint4*)&sBl[nb][br][bq]     = rbl0;
                *(uint4*)&sBl[nb][br][bq + 8] = rbl1;
                __syncthreads();
            }
        }

        {
            const int r0 = wr * 16 + gid;
            #pragma unroll
            for (int nt = 0; nt < 4; nt++) {
                const int c0 = wc * 32 + nt * 8 + kp * 2;
                sD[r0][c0]         = acc[nt][0];
                sD[r0][c0 + 1]     = acc[nt][1];
                sD[r0 + 8][c0]     = acc[nt][2];
                sD[r0 + 8][c0 + 1] = acc[nt][3];
            }
        }
        __syncthreads();
        {
            int s = tid >> 3, cg = (tid & 7) * 16;
            long ob = offOut[s];
            if (ob >= 0) {
                #pragma unroll
                for (int i = 0; i < 16; i++)
                    atomicAdd(&out[ob + cg + i], sD[s][cg + i]);
            }
        }
    } else {
        int idx = (e - 288) * 256 + tid;
        if (idx >= Bsz * TOT) return;
        int b = idx / TOT, t = idx - b * TOT;
        float v;
        if (t < NV) {
            int i, w;
            if (t < 762)      { i = t / 3; w = t - 3 * i; }
            else if (t < 764) { i = 254;  w = t - 762;   }
            else              { i = 255;  w = 0;         }
            int j = i + w;
            v = g_L[b * Ssz + i] + g_L[512 + b * Ssz + j] + g_L[1024 + w] + g_L[1027];
        } else {
            v = g_L[1027];
        }
        out[idx] = v;
    }
}

// ---------------------------------------------------------------------------
// Side stream + events: created once at module load (host objects only; no
// device-memory allocation inside kernel_launch).
// ---------------------------------------------------------------------------
static cudaStream_t g_s2;
static cudaEvent_t g_evF, g_evS1, g_evS2, g_evS3;
static struct StreamInit {
    StreamInit() {
        cudaStreamCreateWithFlags(&g_s2, cudaStreamNonBlocking);
        cudaEventCreateWithFlags(&g_evF,  cudaEventDisableTiming);
        cudaEventCreateWithFlags(&g_evS1, cudaEventDisableTiming);
        cudaEventCreateWithFlags(&g_evS2, cudaEventDisableTiming);
        cudaEventCreateWithFlags(&g_evS3, cudaEventDisableTiming);
    }
} g_streamInit;

// ---------------------------------------------------------------------------
extern "C" void kernel_launch(void* const* d_in, const int* in_sizes, int n_in,
                              void* d_out, int out_size)
{
    const float* hidden    = (const float*)d_in[0];
    const float* width_emb = (const float*)d_in[1];
    const float* w_span    = (const float*)d_in[2];
    const float* b_span    = (const float*)d_in[3];
    const float* w_cls     = (const float*)d_in[4];
    const float* b_cls     = (const float*)d_in[5];
    const float* w_p1      = (const float*)d_in[6];
    const float* b_p1      = (const float*)d_in[7];
    const float* w_p2      = (const float*)d_in[8];
    const float* b_p2      = (const float*)d_in[9];
    float* out = (float*)d_out;

    // fork side stream from the (capturing) main stream
    cudaEventRecord(g_evF, 0);
    cudaStreamWaitEvent(g_s2, g_evF, 0);

    // main: hidden + w_span conversions
    M0_k<<<480, 256>>>(hidden, w_span);
    // side: w_p1/w_p2 transposes, W3, cpad, valid-row init
    S1_k<<<264, 256, 0, g_s2>>>(w_p1, w_p2, width_emb, w_span,
                                b_span, b_p1, b_p2, out);
    cudaEventRecord(g_evS1, g_s2);

    // main: GEMM1
    M1_k<<<192, 128>>>();

    // side: C rows + projpad (needs W3/cpad, same stream order), then fillpad
    S2_k<<<38, 128, 0, g_s2>>>(b_span, w_p1, b_p1, w_p2, b_p2);
    cudaEventRecord(g_evS2, g_s2);
    S3_k<<<2008, 128, 0, g_s2>>>(out);
    cudaEventRecord(g_evS3, g_s2);

    // main: GEMM2 + dots (needs w_p1^T from S1)
    cudaStreamWaitEvent(0, g_evS1, 0);
    M2_k<<<449, 128>>>(w_cls, b_cls, b_span);

    // main: spanproj + logits (needs C/projpad-init/w_p2^T from S1/S2)
    cudaStreamWaitEvent(0, g_evS2, 0);
    M3_k<<<545, 256>>>(out);

    // join: fillpad must complete before harness reads out
    cudaStreamWaitEvent(0, g_evS3, 0);
}

// round 17
// speedup vs baseline: 1.0507x; 1.0507x over previous
#include <cuda_runtime.h>
#include <cuda_bf16.h>
#include <cstdint>

#define Dsz 768
#define Bsz 2
#define Ssz 256
#define NV  765
#define TOT 32896
#define PD  128
#define HS  393216L        // 512*768 (z stride in elems)
#define WS  589824L        // 768*768
#define PADROWS (TOT - NV) // 32131

typedef __nv_bfloat16 bf16;
typedef __nv_bfloat162 bf162;

// ---------------- scratch (device globals; no allocation) ------------------
__device__ __align__(16) bf16 g_hh[Bsz*Ssz*Dsz], g_hl[Bsz*Ssz*Dsz];     // hidden hi/lo
__device__ __align__(16) bf16 g_wsTh[2*WS],      g_wsTl[2*WS];          // w_span[z]^T hi/lo
__device__ __align__(16) bf16 g_wp1Th[WS],       g_wp1Tl[WS];           // w_p1^T hi/lo
__device__ __align__(16) bf16 g_wp2Th[PD*Dsz],   g_wp2Tl[PD*Dsz];       // w_p2^T hi/lo
__device__ __align__(16) bf16 g_Hh[2*Bsz*Ssz*Dsz], g_Hl[2*Bsz*Ssz*Dsz]; // H hi/lo
__device__ __align__(16) float g_A[2*Bsz*Ssz*Dsz];                      // A fp32
__device__ float g_W3[3*Dsz];
__device__ float g_C[4*Dsz];          // 0..2: (W3[w]+b_span)@w_p1+b_p1 ; 3: cpad
__device__ float g_L[1028];
__device__ __align__(16) float g_projpad[PD];
__device__ float g_zero[Dsz];

// ---------------------------------------------------------------------------
__device__ __forceinline__ void mma_bf16(float* c, const unsigned* a,
                                         const unsigned* b) {
    asm volatile(
        "mma.sync.aligned.m16n8k16.row.col.f32.bf16.bf16.f32 "
        "{%0,%1,%2,%3}, {%4,%5,%6,%7}, {%8,%9}, {%0,%1,%2,%3};"
        : "+f"(c[0]), "+f"(c[1]), "+f"(c[2]), "+f"(c[3])
        : "r"(a[0]), "r"(a[1]), "r"(a[2]), "r"(a[3]), "r"(b[0]), "r"(b[1]));
}

#define KST 24

// ---------------------------------------------------------------------------
// MMA GEMM tile (validated R9/R12/R15): D[64x64] = A[64x768] * B[64x768]^T
// bf16 hi/lo split, fp32 accum.  128 thr, 4 warps 32x32, 48 chunks of 16-K.
// ---------------------------------------------------------------------------
__device__ void tmma_body(int e,
    const bf16* __restrict__ Ah0, const bf16* __restrict__ Al0, long aZ,
    const bf16* __restrict__ Bh0, const bf16* __restrict__ Bl0, long bZ,
    int outMode)
{
    __shared__ __align__(16) bf16 sA[2][2][64][KST];
    __shared__ __align__(16) bf16 sB[2][2][64][KST];

    const int z = e / 96, r = e % 96;
    const int row0 = (r / 12) * 64, n0 = (r % 12) * 64;
    const bf16* Ah = Ah0 + (long)z * aZ;
    const bf16* Al = Al0 + (long)z * aZ;
    const bf16* Bh = Bh0 + (long)z * bZ;
    const bf16* Bl = Bl0 + (long)z * bZ;

    const int tid = threadIdx.x, wid = tid >> 5, lane = tid & 31;
    const int wr = wid >> 1, wc = wid & 1;
    const int gid = lane >> 2, kp = lane & 3;

    const int lr = tid >> 1, lh = (tid & 1) * 8;
    const long aoff = (long)(row0 + lr) * Dsz + lh;
    const long boff = (long)(n0 + lr) * Dsz + lh;

    float acc[2][4][4] = {};
    uint4 pAh, pAl, pBh, pBl;

    pAh = *(const uint4*)(Ah + aoff);
    pAl = *(const uint4*)(Al + aoff);
    pBh = *(const uint4*)(Bh + boff);
    pBl = *(const uint4*)(Bl + boff);
    *(uint4*)&sA[0][0][lr][lh] = pAh;
    *(uint4*)&sA[0][1][lr][lh] = pAl;
    *(uint4*)&sB[0][0][lr][lh] = pBh;
    *(uint4*)&sB[0][1][lr][lh] = pBl;
    __syncthreads();

    for (int it = 0; it < 48; it++) {
        const int cur = it & 1;
        if (it + 1 < 48) {
            const int kb = (it + 1) * 16;
            pAh = *(const uint4*)(Ah + aoff + kb);
            pAl = *(const uint4*)(Al + aoff + kb);
            pBh = *(const uint4*)(Bh + boff + kb);
            pBl = *(const uint4*)(Bl + boff + kb);
        }

        unsigned ah[2][4], al[2][4], bh[4][2], bl[4][2];
        #pragma unroll
        for (int mt = 0; mt < 2; mt++) {
            const int r0 = wr * 32 + mt * 16 + gid;
            ah[mt][0] = *(const unsigned*)&sA[cur][0][r0][kp * 2];
            ah[mt][1] = *(const unsigned*)&sA[cur][0][r0 + 8][kp * 2];
            ah[mt][2] = *(const unsigned*)&sA[cur][0][r0][kp * 2 + 8];
            ah[mt][3] = *(const unsigned*)&sA[cur][0][r0 + 8][kp * 2 + 8];
            al[mt][0] = *(const unsigned*)&sA[cur][1][r0][kp * 2];
            al[mt][1] = *(const unsigned*)&sA[cur][1][r0 + 8][kp * 2];
            al[mt][2] = *(const unsigned*)&sA[cur][1][r0][kp * 2 + 8];
            al[mt][3] = *(const unsigned*)&sA[cur][1][r0 + 8][kp * 2 + 8];
        }
        #pragma unroll
        for (int nt = 0; nt < 4; nt++) {
            const int rb = wc * 32 + nt * 8 + gid;
            bh[nt][0] = *(const unsigned*)&sB[cur][0][rb][kp * 2];
            bh[nt][1] = *(const unsigned*)&sB[cur][0][rb][kp * 2 + 8];
            bl[nt][0] = *(const unsigned*)&sB[cur][1][rb][kp * 2];
            bl[nt][1] = *(const unsigned*)&sB[cur][1][rb][kp * 2 + 8];
        }
        #pragma unroll
        for (int mt = 0; mt < 2; mt++)
            #pragma unroll
            for (int nt = 0; nt < 4; nt++) {
                mma_bf16(acc[mt][nt], ah[mt], bh[nt]);
                mma_bf16(acc[mt][nt], ah[mt], bl[nt]);
                mma_bf16(acc[mt][nt], al[mt], bh[nt]);
            }

        if (it + 1 < 48) {
            const int nb = cur ^ 1;
            *(uint4*)&sA[nb][0][lr][lh] = pAh;
            *(uint4*)&sA[nb][1][lr][lh] = pAl;
            *(uint4*)&sB[nb][0][lr][lh] = pBh;
            *(uint4*)&sB[nb][1][lr][lh] = pBl;
            __syncthreads();
        }
    }

    #pragma unroll
    for (int mt = 0; mt < 2; mt++) {
        const int grow = row0 + wr * 32 + mt * 16 + gid;
        const long gr0 = ((long)z * 512 + grow) * Dsz;
        const long gr1 = gr0 + 8L * Dsz;
        #pragma unroll
        for (int nt = 0; nt < 4; nt++) {
            const int gc = n0 + wc * 32 + nt * 8 + kp * 2;
            const float* cc = acc[mt][nt];
            if (outMode == 1) {
                bf162 h01 = __floats2bfloat162_rn(cc[0], cc[1]);
                bf162 l01 = __floats2bfloat162_rn(cc[0] - __low2float(h01),
                                                  cc[1] - __high2float(h01));
                bf162 h23 = __floats2bfloat162_rn(cc[2], cc[3]);
                bf162 l23 = __floats2bfloat162_rn(cc[2] - __low2float(h23),
                                                  cc[3] - __high2float(h23));
                *(bf162*)&g_Hh[gr0 + gc] = h01;
                *(bf162*)&g_Hl[gr0 + gc] = l01;
                *(bf162*)&g_Hh[gr1 + gc] = h23;
                *(bf162*)&g_Hl[gr1 + gc] = l23;
            } else {
                float2 v0 = { cc[0], cc[1] }, v1 = { cc[2], cc[3] };
                *(float2*)&g_A[gr0 + gc] = v0;
                *(float2*)&g_A[gr1 + gc] = v1;
            }
        }
    }
}

// ---------------------------------------------------------------------------
// GEMV helper (256 thr)
// ---------------------------------------------------------------------------
__device__ __forceinline__ void gemv256(
    const float* __restrict__ a1, const float* __restrict__ a2, int mode,
    const float* __restrict__ W, int ldw,
    const float* __restrict__ bias, float* __restrict__ out,
    int n0, char* raw)
{
    float (*red)[64] = (float(*)[64])raw;
    const int tid = threadIdx.x;
    const int nl = tid & 63, kg = tid >> 6;
    const int n = n0 + nl;
    float s = 0.f;
    const int k0 = kg * 192;
    #pragma unroll 8
    for (int t = 0; t < 192; t++) {
        int k = k0 + t;
        float av = a1[k];
        if (mode == 1) av += a2[k];
        else if (mode == 2) av = fmaxf(av, 0.f);
        s += av * W[(long)k * ldw + n];
    }
    red[kg][nl] = s;
    __syncthreads();
    if (kg == 0)
        out[n] = red[0][nl] + red[1][nl] + red[2][nl] + red[3][nl] + bias[n];
}

// ---------------------------------------------------------------------------
// P0 (256 thr): [0,432) w_span/w_p1 T+cvt ; [432,624) hidden cvt ;
//   [624,660) W3 ; [660,672) cpad ; [672,696) w_p2 T ;
//   [696,705) g_C rows0-2 <- b_p1 ; [705,706) g_projpad <- b_p2
// ---------------------------------------------------------------------------
__global__ void P0_k(const float* __restrict__ hidden,
                     const float* __restrict__ w_span,
                     const float* __restrict__ w_p1,
                     const float* __restrict__ w_p2,
                     const float* __restrict__ width_emb,
                     const float* __restrict__ b_span,
                     const float* __restrict__ b_p1,
                     const float* __restrict__ b_p2)
{
    __shared__ __align__(16) char raw[64 * 65 * 4];
    int e = blockIdx.x, tid = threadIdx.x;
    if (e < 432) {
        int m = e / 144, t = e % 144;
        int tr = t / 12, tc = t % 12;
        const float* src = (m < 2) ? (w_span + (long)m * WS) : w_p1;
        bf16* dh = (m < 2) ? (g_wsTh + (long)m * WS) : g_wp1Th;
        bf16* dl = (m < 2) ? (g_wsTl + (long)m * WS) : g_wp1Tl;
        int n0 = tr * 64, k0 = tc * 64;
        float (*ts)[65] = (float(*)[65])raw;
        {
            int r = tid >> 2, cs = (tid & 3) * 16;
            const float* sp = src + (long)(k0 + r) * Dsz + n0 + cs;
            #pragma unroll
            for (int i = 0; i < 16; i++) ts[r][cs + i] = sp[i];
        }
        __syncthreads();
        {
            int rr = tid >> 2, ks = (tid & 3) * 16;
            long go = (long)(n0 + rr) * Dsz + k0 + ks;
            #pragma unroll
            for (int i = 0; i < 16; i++) {
                float x = ts[ks + i][rr];
                bf16 h = __float2bfloat16(x);
                dh[go + i] = h;
                dl[go + i] = __float2bfloat16(x - __bfloat162float(h));
            }
        }
    } else if (e < 624) {
        long base = (long)(e - 432) * 2048 + tid * 8;
        float4 a = *(const float4*)(hidden + base);
        float4 b = *(const float4*)(hidden + base + 4);
        float xs[8] = { a.x, a.y, a.z, a.w, b.x, b.y, b.z, b.w };
        __align__(16) bf16 h8[8], l8[8];
        #pragma unroll
        for (int i = 0; i < 8; i++) {
            bf16 h = __float2bfloat16(xs[i]);
            h8[i] = h;
            l8[i] = __float2bfloat16(xs[i] - __bfloat162float(h));
        }
        *(uint4*)(g_hh + base) = *(const uint4*)h8;
        *(uint4*)(g_hl + base) = *(const uint4*)l8;
    } else if (e < 660) {
        int g = e - 624, m = g / 12, nb = g % 12;
        gemv256(width_emb + m * Dsz, nullptr, 0,
                w_span + 2L * Dsz * Dsz, Dsz,
                g_zero, g_W3 + m * Dsz, nb * 64, raw);
    } else if (e < 672) {
        int nb = e - 660;
        gemv256(b_span, nullptr, 0, w_p1, Dsz, b_p1, g_C + 3 * Dsz,
                nb * 64, raw);
    } else if (e < 696) {
        int t = e - 672;                     // 24 tiles: w_p2 -> [128][768]
        int k0 = (t >> 1) * 64, n0 = (t & 1) * 64;
        float (*ts)[65] = (float(*)[65])raw;
        {
            int r = tid >> 2, cs = (tid & 3) * 16;
            const float* sp = w_p2 + (long)(k0 + r) * PD + n0 + cs;
            #pragma unroll
            for (int i = 0; i < 16; i++) ts[r][cs + i] = sp[i];
        }
        __syncthreads();
        {
            int rr = tid >> 2, ks = (tid & 3) * 16;
            long go = (long)(n0 + rr) * Dsz + k0 + ks;
            #pragma unroll
            for (int i = 0; i < 16; i++) {
                float x = ts[ks + i][rr];
                bf16 h = __float2bfloat16(x);
                g_wp2Th[go + i] = h;
                g_wp2Tl[go + i] = __float2bfloat16(x - __bfloat162float(h));
            }
        }
    } else if (e < 705) {
        int i = (e - 696) * 256 + tid;       // 2304 elems
        if (i < 3 * Dsz) g_C[i] = b_p1[i - (i / Dsz) * Dsz];
    } else {
        if (tid < PD) g_projpad[tid] = b_p2[tid];
    }
}

// ---------------------------------------------------------------------------
// P1 (128 thr): [0,192) MMA GEMM1 (H) ;
//   [192,336) C rows 0-2 K-split x4 atomic ; [336,344) projpad K-split x4
// ---------------------------------------------------------------------------
__global__ __launch_bounds__(128, 4) void P1_k(
    const float* __restrict__ b_span, const float* __restrict__ w_p1,
    const float* __restrict__ w_p2)
{
    int e = blockIdx.x, tid = threadIdx.x;
    if (e < 192) {
        tmma_body(e, g_hh, g_hl, 0L, g_wsTh, g_wsTl, WS, 1);
    } else if (e < 336) {
        int g = e - 192;                     // 144 = 36 gn x 4 ks
        int ks = g & 3, gn = g >> 2;
        int m = gn / 12, nb = gn % 12;
        __shared__ float red[2][64];
        int nl = tid & 63, kg = tid >> 6;
        int n = nb * 64 + nl;
        int k0 = ks * 192 + kg * 96;
        float s = 0.f;
        #pragma unroll 8
        for (int t = 0; t < 96; t++) {
            int k = k0 + t;
            s += (g_W3[m * Dsz + k] + b_span[k]) * w_p1[(long)k * Dsz + n];
        }
        red[kg][nl] = s;
        __syncthreads();
        if (kg == 0) atomicAdd(&g_C[m * Dsz + n], red[0][nl] + red[1][nl]);
    } else {
        int g = e - 336;                     // 8 = 2 nb x 4 ks
        int nb = g >> 2, ks = g & 3;
        __shared__ float red[2][64];
        int nl = tid & 63, kg = tid >> 6;
        int n = nb * 64 + nl;
        int k0 = ks * 192 + kg * 96;
        float s = 0.f;
        #pragma unroll 8
        for (int t = 0; t < 96; t++) {
            int k = k0 + t;
            s += fmaxf(g_C[3 * Dsz + k], 0.f) * w_p2[(long)k * PD + n];
        }
        red[kg][nl] = s;
        __syncthreads();
        if (kg == 0) atomicAdd(&g_projpad[n], red[0][nl] + red[1][nl]);
    }
}

// ---------------------------------------------------------------------------
// P2 (128 thr): [0,192) MMA GEMM2 (A) ; [192,449) dots ;
//               [449,497) valid-row b_p2 init
// ---------------------------------------------------------------------------
__global__ __launch_bounds__(128, 4) void P2_k(
    const float* __restrict__ w_cls, const float* __restrict__ b_cls,
    const float* __restrict__ b_span, const float* __restrict__ b_p2,
    float* __restrict__ out)
{
    int e = blockIdx.x;
    int tid = threadIdx.x;
    if (e < 192) {
        tmma_body(e, g_Hh, g_Hl, HS, g_wp1Th, g_wp1Tl, 0L, 2);
    } else if (e < 449) {
        int gw = (e - 192) * 4 + (tid >> 5);
        int lane = tid & 31;
        if (gw >= 1028) return;
        float s = 0.f;
        if (gw < 1024) {
            int z = gw >> 9, row = gw & 511;
            const bf16* bh = g_Hh + (long)z * HS + (long)row * Dsz;
            const bf16* bl = g_Hl + (long)z * HS + (long)row * Dsz;
            for (int k = lane; k < Dsz; k += 32)
                s += (__bfloat162float(bh[k]) + __bfloat162float(bl[k])) * w_cls[k];
        } else {
            const float* v = (gw < 1027) ? (g_W3 + (gw - 1024) * Dsz) : b_span;
            for (int k = lane; k < Dsz; k += 32) s += v[k] * w_cls[k];
        }
        #pragma unroll
        for (int o = 16; o > 0; o >>= 1) s += __shfl_down_sync(0xffffffffu, s, o);
        if (lane == 0) g_L[gw] = s + (gw == 1027 ? b_cls[0] : 0.f);
    } else {
        const long NVAL4 = (long)2 * NV * 32;        // 48960
        long base = (long)(e - 449) * 1024 + tid;
        #pragma unroll
        for (int i = 0; i < 8; i++) {
            long p = base + (long)i * 128;
            if (p < NVAL4) {
                int r = (int)(p >> 5), c = (int)(p & 31);
                int b = r / NV;
                int kv = r - b * NV;
                float4 val = ((const float4*)b_p2)[c];
                long f4 = (long)(Bsz * TOT) / 4 + ((long)b * TOT + kv) * (PD / 4) + c;
                ((float4*)out)[f4] = val;
            }
        }
    }
}

// ---------------------------------------------------------------------------
// P3 (256 thr): [0,288) spanproj MMA (K-split x6, atomicAdd) ;
//               [288,545) logits ; [545,1549) fillpad
// ---------------------------------------------------------------------------
#define KST2 40
__global__ __launch_bounds__(256) void P3_k(float* __restrict__ out)
{
    int e = blockIdx.x;
    int tid = threadIdx.x;
    if (e < 288) {
        __shared__ __align__(16) bf16 sXh[2][32][KST2], sXl[2][32][KST2];
        __shared__ __align__(16) bf16 sBh[2][128][KST2], sBl[2][128][KST2];
        __shared__ float sD[32][132];
        __shared__ int offA1[32], offA2[32], offC[32];
        __shared__ long offOut[32];

        const int ks6 = e % 6, sg = e / 6;
        const int kbase = ks6 * 128;
        const int wid = tid >> 5, lane = tid & 31;
        const int wr = wid >> 2, wc = wid & 3;
        const int gid = lane >> 2, kp = lane & 3;

        if (tid < 32) {
            int msp = sg * 32 + tid;
            int b = 0, i = 0, w = 0;
            bool valid = msp < 2 * NV;
            int kv = 0;
            if (valid) {
                b = msp / NV; kv = msp - b * NV;
                if (kv < 762)      { i = kv / 3; w = kv - 3 * i; }
                else if (kv < 764) { i = 254;   w = kv - 762;   }
                else               { i = 255;   w = 0;          }
            }
            int j = i + w;
            offA1[tid] = (b * Ssz + i) * Dsz;
            offA2[tid] = (int)HS + (b * Ssz + j) * Dsz;
            offC[tid]  = w * Dsz;
            offOut[tid] = valid ? ((long)Bsz * TOT + ((long)b * TOT + kv) * PD) : -1L;
        }
        __syncthreads();

        const int xs = tid >> 3, xq = (tid & 7) * 4;
        const int br = tid >> 1, bq = (tid & 1) * 16;
        const bf16* pbh = g_wp2Th + (long)br * Dsz;
        const bf16* pbl = g_wp2Tl + (long)br * Dsz;

        float acc[4][4] = {};
        __align__(8) bf16 xh4[4], xl4[4];
        uint4 rbh0, rbh1, rbl0, rbl1;

        {
            const int kb = kbase;
            const float* p1 = g_A + offA1[xs] + kb + xq;
            const float* p2 = g_A + offA2[xs] + kb + xq;
            const float* pc = g_C + offC[xs] + kb + xq;
            #pragma unroll
            for (int i = 0; i < 4; i++) {
                float x = fmaxf(p1[i] + p2[i] + pc[i], 0.f);
                bf16 h = __float2bfloat16(x);
                xh4[i] = h;
                xl4[i] = __float2bfloat16(x - __bfloat162float(h));
            }
            rbh0 = *(const uint4*)(pbh + kb + bq);
            rbh1 = *(const uint4*)(pbh + kb + bq + 8);
            rbl0 = *(const uint4*)(pbl + kb + bq);
            rbl1 = *(const uint4*)(pbl + kb + bq + 8);
            *(uint2*)&sXh[0][xs][xq] = *(const uint2*)xh4;
            *(uint2*)&sXl[0][xs][xq] = *(const uint2*)xl4;
            *(uint4*)&sBh[0][br][bq]     = rbh0;
            *(uint4*)&sBh[0][br][bq + 8] = rbh1;
            *(uint4*)&sBl[0][br][bq]     = rbl0;
            *(uint4*)&sBl[0][br][bq + 8] = rbl1;
        }
        __syncthreads();

        for (int kc = 0; kc < 4; kc++) {
            const int cur = kc & 1;
            if (kc + 1 < 4) {
                const int kb = kbase + (kc + 1) * 32;
                const float* p1 = g_A + offA1[xs] + kb + xq;
                const float* p2 = g_A + offA2[xs] + kb + xq;
                const float* pc = g_C + offC[xs] + kb + xq;
                #pragma unroll
                for (int i = 0; i < 4; i++) {
                    float x = fmaxf(p1[i] + p2[i] + pc[i], 0.f);
                    bf16 h = __float2bfloat16(x);
                    xh4[i] = h;
                    xl4[i] = __float2bfloat16(x - __bfloat162float(h));
                }
                rbh0 = *(const uint4*)(pbh + kb + bq);
                rbh1 = *(const uint4*)(pbh + kb + bq + 8);
                rbl0 = *(const uint4*)(pbl + kb + bq);
                rbl1 = *(const uint4*)(pbl + kb + bq + 8);
            }

            #pragma unroll
            for (int ks = 0; ks < 2; ks++) {
                const int ko = ks * 16;
                unsigned ah[4], al[4], bh[4][2], bl[4][2];
                {
                    const int r0 = wr * 16 + gid;
                    ah[0] = *(const unsigned*)&sXh[cur][r0][kp * 2 + ko];
                    ah[1] = *(const unsigned*)&sXh[cur][r0 + 8][kp * 2 + ko];
                    ah[2] = *(const unsigned*)&sXh[cur][r0][kp * 2 + 8 + ko];
                    ah[3] = *(const unsigned*)&sXh[cur][r0 + 8][kp * 2 + 8 + ko];
                    al[0] = *(const unsigned*)&sXl[cur][r0][kp * 2 + ko];
                    al[1] = *(const unsigned*)&sXl[cur][r0 + 8][kp * 2 + ko];
                    al[2] = *(const unsigned*)&sXl[cur][r0][kp * 2 + 8 + ko];
                    al[3] = *(const unsigned*)&sXl[cur][r0 + 8][kp * 2 + 8 + ko];
                }
                #pragma unroll
                for (int nt = 0; nt < 4; nt++) {
                    const int rb = wc * 32 + nt * 8 + gid;
                    bh[nt][0] = *(const unsigned*)&sBh[cur][rb][kp * 2 + ko];
                    bh[nt][1] = *(const unsigned*)&sBh[cur][rb][kp * 2 + 8 + ko];
                    bl[nt][0] = *(const unsigned*)&sBl[cur][rb][kp * 2 + ko];
                    bl[nt][1] = *(const unsigned*)&sBl[cur][rb][kp * 2 + 8 + ko];
                }
                #pragma unroll
                for (int nt = 0; nt < 4; nt++) {
                    mma_bf16(acc[nt], ah, bh[nt]);
                    mma_bf16(acc[nt], ah, bl[nt]);
                    mma_bf16(acc[nt], al, bh[nt]);
                }
            }

            if (kc + 1 < 4) {
                const int nb = cur ^ 1;
                *(uint2*)&sXh[nb][xs][xq] = *(const uint2*)xh4;
                *(uint2*)&sXl[nb][xs][xq] = *(const uint2*)xl4;
                *(uint4*)&sBh[nb][br][bq]     = rbh0;
                *(uint4*)&sBh[nb][br][bq + 8] = rbh1;
                *(uint4*)&sBl[nb][br][bq]     = rbl0;
                *(uint4*)&sBl[nb][br][bq + 8] = rbl1;
                __syncthreads();
            }
        }

        {
            const int r0 = wr * 16 + gid;
            #pragma unroll
            for (int nt = 0; nt < 4; nt++) {
                const int c0 = wc * 32 + nt * 8 + kp * 2;
                sD[r0][c0]         = acc[nt][0];
                sD[r0][c0 + 1]     = acc[nt][1];
                sD[r0 + 8][c0]     = acc[nt][2];
                sD[r0 + 8][c0 + 1] = acc[nt][3];
            }
        }
        __syncthreads();
        {
            int s = tid >> 3, cg = (tid & 7) * 16;
            long ob = offOut[s];
            if (ob >= 0) {
                #pragma unroll
                for (int i = 0; i < 16; i++)
                    atomicAdd(&out[ob + cg + i], sD[s][cg + i]);
            }
        }
    } else if (e < 545) {
        int idx = (e - 288) * 256 + tid;
        if (idx >= Bsz * TOT) return;
        int b = idx / TOT, t = idx - b * TOT;
        float v;
        if (t < NV) {
            int i, w;
            if (t < 762)      { i = t / 3; w = t - 3 * i; }
            else if (t < 764) { i = 254;  w = t - 762;   }
            else              { i = 255;  w = 0;         }
            int j = i + w;
            v = g_L[b * Ssz + i] + g_L[512 + b * Ssz + j] + g_L[1024 + w] + g_L[1027];
        } else {
            v = g_L[1027];
        }
        out[idx] = v;
    } else {
        const long NPAD4 = (long)Bsz * PADROWS * 32;
        long base = (long)(e - 545) * 2048 + tid;
        #pragma unroll
        for (int i = 0; i < 8; i++) {
            long p = base + (long)i * 256;
            if (p < NPAD4) {
                int r = (int)(p >> 5), c = (int)(p & 31);
                int b = r / PADROWS;
                int kk = NV + (r - b * PADROWS);
                float4 val = ((const float4*)g_projpad)[c];
                long f4 = (long)(Bsz * TOT) / 4 + ((long)b * TOT + kk) * (PD / 4) + c;
                ((float4*)out)[f4] = val;
            }
        }
    }
}

// ---------------------------------------------------------------------------
extern "C" void kernel_launch(void* const* d_in, const int* in_sizes, int n_in,
                              void* d_out, int out_size)
{
    const float* hidden    = (const float*)d_in[0];
    const float* width_emb = (const float*)d_in[1];
    const float* w_span    = (const float*)d_in[2];
    const float* b_span    = (const float*)d_in[3];
    const float* w_cls     = (const float*)d_in[4];
    const float* b_cls     = (const float*)d_in[5];
    const float* w_p1      = (const float*)d_in[6];
    const float* b_p1      = (const float*)d_in[7];
    const float* w_p2      = (const float*)d_in[8];
    const float* b_p2      = (const float*)d_in[9];
    float* out = (float*)d_out;

    P0_k<<<706, 256>>>(hidden, w_span, w_p1, w_p2, width_emb, b_span, b_p1, b_p2);
    P1_k<<<344, 128>>>(b_span, w_p1, w_p2);
    P2_k<<<497, 128>>>(w_cls, b_cls, b_span, b_p2, out);
    P3_k<<<1549, 256>>>(out);
}